// round 8
// baseline (speedup 1.0000x reference)
#include <cuda_runtime.h>
#include <cuda_fp16.h>
#include <cstdint>

// OnlineHadamard round 8: single-pass fp16 HMMA, A in registers, 2-D warp tiling.
//  NT=384, 12 warps = 6(jt) x 2(mt); each warp: 32 j-rows x 32 m-cols.
//  Per row: prefetch next-row chunks (LDG) -> GEMM(row i) -> butterfly into next B.
// B double-buffered fp16; A (had fp16) loaded once into register fragments.

#define KDIM 172
#define MDIM 64
#define NROW 11008
#define NT 384

#define ASTR 368                    // A row: 352B fp16 pad->368
#define BSTR 144                    // B row: 128B fp16 pad->144
#define A_BYTES (192 * ASTR)        // padded to 192 j-rows: 70656
#define B_BYTES (176 * BSTR)        // 25344 per buffer
#define OFF_B0  (A_BYTES)
#define OFF_B1  (A_BYTES + B_BYTES)
#define SMEM_DYN (A_BYTES + 2 * B_BYTES)   // 121344

__device__ __forceinline__ uint32_t smem_u32(const void* p) {
    uint32_t a;
    asm("{ .reg .u64 t; cvta.to.shared.u64 t, %1; cvt.u32.u64 %0, t; }" : "=r"(a) : "l"(p));
    return a;
}
__device__ __forceinline__ void ldsm_x4(uint32_t* r, uint32_t addr) {
    asm volatile("ldmatrix.sync.aligned.m8n8.x4.shared.b16 {%0,%1,%2,%3}, [%4];"
                 : "=r"(r[0]), "=r"(r[1]), "=r"(r[2]), "=r"(r[3]) : "r"(addr));
}
__device__ __forceinline__ void ldsm_x4t(uint32_t* r, uint32_t addr) {
    asm volatile("ldmatrix.sync.aligned.m8n8.x4.trans.shared.b16 {%0,%1,%2,%3}, [%4];"
                 : "=r"(r[0]), "=r"(r[1]), "=r"(r[2]), "=r"(r[3]) : "r"(addr));
}
__device__ __forceinline__ void mma_f16(float* c, const uint32_t* a, uint32_t b0, uint32_t b1) {
    asm volatile("mma.sync.aligned.m16n8k16.row.col.f32.f16.f16.f32 "
                 "{%0,%1,%2,%3}, {%4,%5,%6,%7}, {%8,%9}, {%0,%1,%2,%3};"
                 : "+f"(c[0]), "+f"(c[1]), "+f"(c[2]), "+f"(c[3])
                 : "r"(a[0]), "r"(a[1]), "r"(a[2]), "r"(a[3]), "r"(b0), "r"(b1));
}

__device__ __forceinline__ void bfly_store(float2 v, char* bbuf, int c, int lane, float scale) {
    float p0 = v.x + v.y, p1 = v.x - v.y;
    #pragma unroll
    for (int s = 0; s < 5; s++) {
        int m = 1 << s;
        float q0 = __shfl_xor_sync(0xffffffffu, p0, m);
        float q1 = __shfl_xor_sync(0xffffffffu, p1, m);
        if (lane & m) { p0 = q0 - p0; p1 = q1 - p1; }
        else          { p0 = p0 + q0; p1 = p1 + q1; }
    }
    __half2 hp = __halves2half2(__float2half_rn(p0 * scale), __float2half_rn(p1 * scale));
    *(uint32_t*)(bbuf + c * BSTR + lane * 4) = *(uint32_t*)&hp;
}

__global__ __launch_bounds__(NT, 1)
void onl_had_r8_kernel(const float* __restrict__ x,
                       const float* __restrict__ had,
                       float* __restrict__ out, int rows)
{
    extern __shared__ char sm[];
    const uint32_t sbase = smem_u32(sm);
    const int tid = threadIdx.x, lane = tid & 31, warp = tid >> 5;

    // ---- one-time: A = had (fp16), zero-padded to 192x176 ----
    for (int idx = tid; idx < 192 * 176; idx += NT) {
        int j = idx / 176, k = idx - j * 176;
        float v = (j < KDIM && k < KDIM) ? had[j * KDIM + k] : 0.0f;
        *(__half*)(sm + j * ASTR + 2 * k) = __float2half_rn(v);
    }
    // zero B pad rows 172..175, both buffers
    for (int idx = tid; idx < 2 * 4 * 64; idx += NT) {
        int b = idx >> 8, r = (idx >> 6) & 3, m = idx & 63;
        char* p = sm + (b ? OFF_B1 : OFF_B0) + (172 + r) * BSTR;
        *(__half*)(p + 2 * m) = __float2half_rn(0.0f);
    }
    __syncthreads();

    const float scale = rsqrtf((float)NROW);
    const int stride = gridDim.x;

    // ---- warp tile: wj in 0..5 (32 j-rows), wm in 0..1 (32 m-cols) ----
    const int wj = warp >> 1, wm = warp & 1;

    // A fragments: 2 j-subtiles x 11 kt, loaded once
    uint32_t a_frag[2][11][4];
    {
        #pragma unroll
        for (int jt2 = 0; jt2 < 2; jt2++) {
            uint32_t a_addr = sbase
                + (uint32_t)((wj * 32 + jt2 * 16) + (lane & 7) + ((lane >> 3) & 1) * 8) * ASTR
                + (uint32_t)((lane >> 4) * 16);
            #pragma unroll
            for (int kt = 0; kt < 11; kt++)
                ldsm_x4(a_frag[jt2][kt], a_addr + kt * 32);
        }
    }

    // B addressing: warp's 32-col half starts at wm*64 bytes
    uint32_t b_lane_off = (uint32_t)((lane & 15) * BSTR + (lane >> 4) * 16 + wm * 64);
    const int eq = lane & 3, er = lane >> 2;

    // FHT: c = warp + 12t, t<15, guard c<172
    int row0 = blockIdx.x;
    if (row0 < rows) {
        const float* xr = x + (size_t)row0 * NROW;
        #pragma unroll
        for (int t = 0; t < 15; t++) {
            int c = warp + 12 * t;
            if (c < KDIM)
                bfly_store(*(const float2*)(xr + (c << 6) + 2 * lane), sm + OFF_B0, c, lane, scale);
        }
    }
    __syncthreads();

    int buf = 0;
    for (int row = row0; row < rows; row += stride) {
        const int nxt = row + stride;
        const bool have_nxt = nxt < rows;
        char* bnext = sm + (buf ? OFF_B0 : OFF_B1);

        // -- prefetch LDGs for next row (retire under GEMM) --
        float2 pf[15];
        if (have_nxt) {
            const float* xn = x + (size_t)nxt * NROW;
            #pragma unroll
            for (int t = 0; t < 15; t++) {
                int c = warp + 12 * t;
                if (c < KDIM) pf[t] = *(const float2*)(xn + (c << 6) + 2 * lane);
            }
        }

        // -------- GEMM row i: 32j x 32m per warp --------
        uint32_t bbase = sbase + (buf ? OFF_B1 : OFF_B0) + b_lane_off;
        float acc[2][4][4];
        #pragma unroll
        for (int jt2 = 0; jt2 < 2; jt2++)
            #pragma unroll
            for (int n = 0; n < 4; n++)
                acc[jt2][n][0] = acc[jt2][n][1] = acc[jt2][n][2] = acc[jt2][n][3] = 0.f;

        #pragma unroll
        for (int kt = 0; kt < 11; kt++) {
            uint32_t bk = bbase + (uint32_t)(kt * 16 * BSTR);
            uint32_t b0[4], b1[4];
            ldsm_x4t(b0, bk);        // cols wm*32 + 0..15
            ldsm_x4t(b1, bk + 32);   // cols wm*32 + 16..31
            #pragma unroll
            for (int jt2 = 0; jt2 < 2; jt2++) {
                mma_f16(acc[jt2][0], a_frag[jt2][kt], b0[0], b0[1]);
                mma_f16(acc[jt2][1], a_frag[jt2][kt], b0[2], b0[3]);
                mma_f16(acc[jt2][2], a_frag[jt2][kt], b1[0], b1[1]);
                mma_f16(acc[jt2][3], a_frag[jt2][kt], b1[2], b1[3]);
            }
        }

        // -------- epilogue: store 32j x 32m patch --------
        {
            float* orow = out + (size_t)row * NROW + wm * 32 + eq * 2;
            #pragma unroll
            for (int jt2 = 0; jt2 < 2; jt2++) {
                int j1 = wj * 32 + jt2 * 16 + er;
                int j2 = j1 + 8;
                if (j1 < KDIM) {
                    float* o1 = orow + j1 * MDIM;
                    #pragma unroll
                    for (int n = 0; n < 4; n++)
                        *(float2*)(o1 + n * 8) = make_float2(acc[jt2][n][0], acc[jt2][n][1]);
                }
                if (j2 < KDIM) {
                    float* o2 = orow + j2 * MDIM;
                    #pragma unroll
                    for (int n = 0; n < 4; n++)
                        *(float2*)(o2 + n * 8) = make_float2(acc[jt2][n][2], acc[jt2][n][3]);
                }
            }
        }

        // -- butterfly next row's chunks from prefetched regs --
        if (have_nxt) {
            #pragma unroll
            for (int t = 0; t < 15; t++) {
                int c = warp + 12 * t;
                if (c < KDIM) bfly_store(pf[t], bnext, c, lane, scale);
            }
        }
        buf ^= 1;
        __syncthreads();
    }
}

extern "C" void kernel_launch(void* const* d_in, const int* in_sizes, int n_in,
                              void* d_out, int out_size) {
    const float* x   = (const float*)d_in[0];
    const float* had = (const float*)d_in[1];
    float* out = (float*)d_out;
    int rows = in_sizes[0] / NROW;

    cudaFuncSetAttribute(onl_had_r8_kernel,
                         cudaFuncAttributeMaxDynamicSharedMemorySize, SMEM_DYN);
    int grid = rows < 152 ? rows : 152;
    onl_had_r8_kernel<<<grid, NT, SMEM_DYN>>>(x, had, out, rows);
}

// round 10
// speedup vs baseline: 1.1750x; 1.1750x over previous
#include <cuda_runtime.h>
#include <cuda_fp16.h>
#include <cstdint>

// OnlineHadamard round 10 (= r9 + compile fix): r8 GEMM (fp16 single-pass,
// A-in-regs, 6x2 warp tile) + restructured FHT: 8 elems/thread, 3 shfl stages.

#define KDIM 172
#define MDIM 64
#define NROW 11008
#define NT 384

#define ASTR 368
#define BSTR 144
#define A_BYTES (192 * ASTR)
#define B_BYTES (176 * BSTR)
#define OFF_B0  (A_BYTES)
#define OFF_B1  (A_BYTES + B_BYTES)
#define SMEM_DYN (A_BYTES + 2 * B_BYTES)   // 121344
#define NQUAD 43                            // 172/4 chunk-quads

__device__ __forceinline__ uint32_t smem_u32(const void* p) {
    uint32_t a;
    asm("{ .reg .u64 t; cvta.to.shared.u64 t, %1; cvt.u32.u64 %0, t; }" : "=r"(a) : "l"(p));
    return a;
}
__device__ __forceinline__ uint32_t h2_u32(__half2 h) {
    uint32_t u;
    *(__half2*)&u = h;
    return u;
}
__device__ __forceinline__ void ldsm_x4(uint32_t* r, uint32_t addr) {
    asm volatile("ldmatrix.sync.aligned.m8n8.x4.shared.b16 {%0,%1,%2,%3}, [%4];"
                 : "=r"(r[0]), "=r"(r[1]), "=r"(r[2]), "=r"(r[3]) : "r"(addr));
}
__device__ __forceinline__ void ldsm_x4t(uint32_t* r, uint32_t addr) {
    asm volatile("ldmatrix.sync.aligned.m8n8.x4.trans.shared.b16 {%0,%1,%2,%3}, [%4];"
                 : "=r"(r[0]), "=r"(r[1]), "=r"(r[2]), "=r"(r[3]) : "r"(addr));
}
__device__ __forceinline__ void mma_f16(float* c, const uint32_t* a, uint32_t b0, uint32_t b1) {
    asm volatile("mma.sync.aligned.m16n8k16.row.col.f32.f16.f16.f32 "
                 "{%0,%1,%2,%3}, {%4,%5,%6,%7}, {%8,%9}, {%0,%1,%2,%3};"
                 : "+f"(c[0]), "+f"(c[1]), "+f"(c[2]), "+f"(c[3])
                 : "r"(a[0]), "r"(a[1]), "r"(a[2]), "r"(a[3]), "r"(b0), "r"(b1));
}

// FHT64 with 8 elements/thread (8 lanes per chunk). tg = lane&7.
// Thread holds m = tg*4 + i (lo) and m = 32 + tg*4 + i (hi), i<4.
__device__ __forceinline__ void bfly8_store(float4 lo, float4 hi, char* bbuf,
                                            int c, int tg, float scale) {
    float v[8] = {lo.x, lo.y, lo.z, lo.w, hi.x, hi.y, hi.z, hi.w};
    float t;
    // distance 32 (lo<->hi)
    #pragma unroll
    for (int i = 0; i < 4; i++) { t = v[i]; v[i] = t + v[i+4]; v[i+4] = t - v[i+4]; }
    // distance 1
    #pragma unroll
    for (int g = 0; g < 8; g += 2) { t = v[g]; v[g] = t + v[g+1]; v[g+1] = t - v[g+1]; }
    // distance 2
    #pragma unroll
    for (int b = 0; b < 8; b += 4)
        #pragma unroll
        for (int i = 0; i < 2; i++) {
            t = v[b+i]; v[b+i] = t + v[b+i+2]; v[b+i+2] = t - v[b+i+2];
        }
    // distances 4, 8, 16 -> lane xor 1, 2, 4 (within 8-lane groups)
    #pragma unroll
    for (int s = 1; s <= 4; s <<= 1) {
        bool up = (tg & s) != 0;
        #pragma unroll
        for (int i = 0; i < 8; i++) {
            float q = __shfl_xor_sync(0xffffffffu, v[i], s);
            v[i] = up ? (q - v[i]) : (v[i] + q);
        }
    }
    // scale, convert, store: 4 halves at m=tg*4, 4 at m=32+tg*4
    uint32_t h01 = h2_u32(__floats2half2_rn(v[0]*scale, v[1]*scale));
    uint32_t h23 = h2_u32(__floats2half2_rn(v[2]*scale, v[3]*scale));
    uint32_t h45 = h2_u32(__floats2half2_rn(v[4]*scale, v[5]*scale));
    uint32_t h67 = h2_u32(__floats2half2_rn(v[6]*scale, v[7]*scale));
    *(uint2*)(bbuf + c * BSTR + tg * 8)      = make_uint2(h01, h23);
    *(uint2*)(bbuf + c * BSTR + 64 + tg * 8) = make_uint2(h45, h67);
}

__global__ __launch_bounds__(NT, 1)
void onl_had_r10_kernel(const float* __restrict__ x,
                        const float* __restrict__ had,
                        float* __restrict__ out, int rows)
{
    extern __shared__ char sm[];
    const uint32_t sbase = smem_u32(sm);
    const int tid = threadIdx.x, lane = tid & 31, warp = tid >> 5;
    const int tg = lane & 7, g = lane >> 3;

    // ---- one-time: A = had (fp16), zero-padded to 192x176 ----
    for (int idx = tid; idx < 192 * 176; idx += NT) {
        int j = idx / 176, k = idx - j * 176;
        float v = (j < KDIM && k < KDIM) ? had[j * KDIM + k] : 0.0f;
        *(__half*)(sm + j * ASTR + 2 * k) = __float2half_rn(v);
    }
    for (int idx = tid; idx < 2 * 4 * 64; idx += NT) {
        int b = idx >> 8, r = (idx >> 6) & 3, m = idx & 63;
        char* p = sm + (b ? OFF_B1 : OFF_B0) + (172 + r) * BSTR;
        *(__half*)(p + 2 * m) = __float2half_rn(0.0f);
    }
    __syncthreads();

    const float scale = rsqrtf((float)NROW);
    const int stride = gridDim.x;

    // ---- warp tile: wj 0..5 (32 j), wm 0..1 (32 m) ----
    const int wj = warp >> 1, wm = warp & 1;
    uint32_t a_frag[2][11][4];
    #pragma unroll
    for (int jt2 = 0; jt2 < 2; jt2++) {
        uint32_t a_addr = sbase
            + (uint32_t)((wj * 32 + jt2 * 16) + (lane & 7) + ((lane >> 3) & 1) * 8) * ASTR
            + (uint32_t)((lane >> 4) * 16);
        #pragma unroll
        for (int kt = 0; kt < 11; kt++)
            ldsm_x4(a_frag[jt2][kt], a_addr + kt * 32);
    }

    uint32_t b_lane_off = (uint32_t)((lane & 15) * BSTR + (lane >> 4) * 16 + wm * 64);
    const int eq = lane & 3, er = lane >> 2;

    // FHT quads: warp handles q = warp + 12p, p<4, q<43; chunk c = 4q + g.
    const uint32_t xoff = (uint32_t)(g * 64 + tg * 4);

    int row0 = blockIdx.x;
    if (row0 < rows) {
        const float* xr = x + (size_t)row0 * NROW;
        #pragma unroll
        for (int p = 0; p < 4; p++) {
            int q = warp + 12 * p;
            if (q < NQUAD) {
                const float* b = xr + q * 256 + xoff;
                bfly8_store(*(const float4*)b, *(const float4*)(b + 32),
                            sm + OFF_B0, 4 * q + g, tg, scale);
            }
        }
    }
    __syncthreads();

    int buf = 0;
    for (int row = row0; row < rows; row += stride) {
        const int nxt = row + stride;
        const bool have_nxt = nxt < rows;
        char* bnext = sm + (buf ? OFF_B0 : OFF_B1);

        // -- prefetch next row's quads (LDG.128 pairs, retire under GEMM) --
        float4 pfl[4], pfh[4];
        if (have_nxt) {
            const float* xn = x + (size_t)nxt * NROW;
            #pragma unroll
            for (int p = 0; p < 4; p++) {
                int q = warp + 12 * p;
                if (q < NQUAD) {
                    const float* b = xn + q * 256 + xoff;
                    pfl[p] = *(const float4*)b;
                    pfh[p] = *(const float4*)(b + 32);
                }
            }
        }

        // -------- GEMM row i: 32j x 32m per warp --------
        uint32_t bbase = sbase + (buf ? OFF_B1 : OFF_B0) + b_lane_off;
        float acc[2][4][4];
        #pragma unroll
        for (int jt2 = 0; jt2 < 2; jt2++)
            #pragma unroll
            for (int n = 0; n < 4; n++)
                acc[jt2][n][0] = acc[jt2][n][1] = acc[jt2][n][2] = acc[jt2][n][3] = 0.f;

        #pragma unroll
        for (int kt = 0; kt < 11; kt++) {
            uint32_t bk = bbase + (uint32_t)(kt * 16 * BSTR);
            uint32_t b0[4], b1[4];
            ldsm_x4t(b0, bk);
            ldsm_x4t(b1, bk + 32);
            #pragma unroll
            for (int jt2 = 0; jt2 < 2; jt2++) {
                mma_f16(acc[jt2][0], a_frag[jt2][kt], b0[0], b0[1]);
                mma_f16(acc[jt2][1], a_frag[jt2][kt], b0[2], b0[3]);
                mma_f16(acc[jt2][2], a_frag[jt2][kt], b1[0], b1[1]);
                mma_f16(acc[jt2][3], a_frag[jt2][kt], b1[2], b1[3]);
            }
        }

        // -------- epilogue: store 32j x 32m patch --------
        {
            float* orow = out + (size_t)row * NROW + wm * 32 + eq * 2;
            #pragma unroll
            for (int jt2 = 0; jt2 < 2; jt2++) {
                int j1 = wj * 32 + jt2 * 16 + er;
                int j2 = j1 + 8;
                if (j1 < KDIM) {
                    float* o1 = orow + j1 * MDIM;
                    #pragma unroll
                    for (int n = 0; n < 4; n++)
                        *(float2*)(o1 + n * 8) = make_float2(acc[jt2][n][0], acc[jt2][n][1]);
                }
                if (j2 < KDIM) {
                    float* o2 = orow + j2 * MDIM;
                    #pragma unroll
                    for (int n = 0; n < 4; n++)
                        *(float2*)(o2 + n * 8) = make_float2(acc[jt2][n][2], acc[jt2][n][3]);
                }
            }
        }

        // -- butterfly next row from prefetched regs (4 independent chains) --
        if (have_nxt) {
            #pragma unroll
            for (int p = 0; p < 4; p++) {
                int q = warp + 12 * p;
                if (q < NQUAD)
                    bfly8_store(pfl[p], pfh[p], bnext, 4 * q + g, tg, scale);
            }
        }
        buf ^= 1;
        __syncthreads();
    }
}

extern "C" void kernel_launch(void* const* d_in, const int* in_sizes, int n_in,
                              void* d_out, int out_size) {
    const float* x   = (const float*)d_in[0];
    const float* had = (const float*)d_in[1];
    float* out = (float*)d_out;
    int rows = in_sizes[0] / NROW;

    cudaFuncSetAttribute(onl_had_r10_kernel,
                         cudaFuncAttributeMaxDynamicSharedMemorySize, SMEM_DYN);
    int grid = rows < 152 ? rows : 152;
    onl_had_r10_kernel<<<grid, NT, SMEM_DYN>>>(x, had, out, rows);
}